// round 2
// baseline (speedup 1.0000x reference)
#include <cuda_runtime.h>

// CostVolumeBlock: horizontal correlation cost volume.
// c1, warp: [B=8, H=192, W=640, C=32] float32 (NHWC, channel-contiguous).
// out: [B, H, W, 37] = 32 c1 passthrough channels + 5 disparity costs
//      cost[o] = mean_c( c1[b,h,w,c] * warp[b,h,w+o-2,c] ), zero outside [0,W).
//
// Strategy: 4 pixels per warp, 8 lanes per pixel, float4 (4 channels) per lane.
//  - Each LDG.128 loads 512 B covering 4 pixels' channels, fully coalesced.
//  - 5 shifted warp-tensor reads per warp; ±2-pixel reuse absorbed by L1/L2.
//  - Per offset: 4 in-thread FMAs + 3-stage butterfly within the 8-lane group.
//  - Stores: 37-float rows (148 B) break float4 alignment for odd pixels, so
//    passthrough uses 4 coalesced STG.32 sweeps; costs one predicated STG.32.
// Memory-bound: ~397 MB compulsory DRAM traffic -> ~57 us floor.

namespace {
constexpr int kB = 8;
constexpr int kH = 192;
constexpr int kW = 640;
constexpr int kC = 32;
constexpr int kSR = 2;
constexpr int kOff = 2 * kSR + 1;            // 5
constexpr int kOutC = kC + kOff;             // 37
constexpr int kPixels = kB * kH * kW;        // 983040
constexpr int kPixPerWarp = 4;
constexpr int kThreads = 256;                // 8 warps -> 32 pixels per block
constexpr int kPixPerBlock = (kThreads / 32) * kPixPerWarp;  // 32
}  // namespace

__global__ __launch_bounds__(kThreads)
void cost_volume_kernel(const float4* __restrict__ c1,
                        const float4* __restrict__ wr,
                        float* __restrict__ out)
{
    const int tid   = blockIdx.x * kThreads + threadIdx.x;
    const int gwarp = tid >> 5;
    const int lane  = threadIdx.x & 31;
    const int grp   = lane >> 3;            // which of 4 pixels in this warp
    const int l8    = lane & 7;             // lane within pixel (8 x float4 = 32 ch)

    const int p = gwarp * kPixPerWarp + grp;    // pixel index
    if (p >= kPixels) return;

    const int w = p % kW;                   // position along width (W%4==0: no straddle)
    const int base4 = p * (kC / 4) + l8;    // float4 index of this lane's channels

    const float4 a = __ldg(&c1[base4]);

    float s0 = 0.f, s1 = 0.f, s2 = 0.f, s3 = 0.f, s4 = 0.f;
    {
        // offset o-2 shifts by (o-2)*32 floats = (o-2)*8 float4s
        float4 v;
        if (w >= 2) {
            v = __ldg(&wr[base4 - 16]);
            s0 = a.x * v.x + a.y * v.y + a.z * v.z + a.w * v.w;
        }
        if (w >= 1) {
            v = __ldg(&wr[base4 - 8]);
            s1 = a.x * v.x + a.y * v.y + a.z * v.z + a.w * v.w;
        }
        v = __ldg(&wr[base4]);
        s2 = a.x * v.x + a.y * v.y + a.z * v.z + a.w * v.w;
        if (w < kW - 1) {
            v = __ldg(&wr[base4 + 8]);
            s3 = a.x * v.x + a.y * v.y + a.z * v.z + a.w * v.w;
        }
        if (w < kW - 2) {
            v = __ldg(&wr[base4 + 16]);
            s4 = a.x * v.x + a.y * v.y + a.z * v.z + a.w * v.w;
        }
    }

    // Butterfly reduction within each 8-lane group (xor 4,2,1 stays in-group).
#pragma unroll
    for (int sh = 4; sh > 0; sh >>= 1) {
        s0 += __shfl_xor_sync(0xffffffffu, s0, sh);
        s1 += __shfl_xor_sync(0xffffffffu, s1, sh);
        s2 += __shfl_xor_sync(0xffffffffu, s2, sh);
        s3 += __shfl_xor_sync(0xffffffffu, s3, sh);
        s4 += __shfl_xor_sync(0xffffffffu, s4, sh);
    }

    const int obase = p * kOutC;

    // Passthrough: 4 coalesced STG.32 sweeps (alignment forbids STG.128 here).
    float* op = out + obase + l8 * 4;
    op[0] = a.x;
    op[1] = a.y;
    op[2] = a.z;
    op[3] = a.w;

    // Costs: lanes 0..4 of each 8-lane group write one mean each.
    if (l8 < kOff) {
        float v = s0;
        if (l8 == 1) v = s1;
        else if (l8 == 2) v = s2;
        else if (l8 == 3) v = s3;
        else if (l8 == 4) v = s4;
        out[obase + kC + l8] = v * (1.0f / 32.0f);
    }
}

extern "C" void kernel_launch(void* const* d_in, const int* in_sizes, int n_in,
                              void* d_out, int out_size)
{
    const float4* c1 = (const float4*)d_in[0];
    const float4* wr = (const float4*)d_in[1];
    // d_in[2] is search_range (int32) — fixed at 2 for this problem's shapes.
    float* out = (float*)d_out;

    const int blocks = (kPixels + kPixPerBlock - 1) / kPixPerBlock;  // 30720
    cost_volume_kernel<<<blocks, kThreads>>>(c1, wr, out);
}